// round 1
// baseline (speedup 1.0000x reference)
#include <cuda_runtime.h>
#include <math.h>
#include <math_constants.h>

// Problem constants
#define NCk 4          // chunks
#define NBk 4          // batch
#define NHk 8          // heads
#define SEQ 4096       // key length
#define TT  4096       // query length
#define CHQ 1024       // queries per chunk
#define ED  64         // head dim
#define MF  128        // nb_features
#define WW  32         // local window
#define NG  128        // NCk*NBk*NHk groups
#define NBLOCK 32      // CHQ/WW query blocks per chunk
#define KVSPLIT 8
#define LOGM 4.852030263919617f

// ---------------- scratch (device globals; no runtime allocation) ----------
__device__ float g_phik[(size_t)NG * SEQ * MF];          // logk, then phi_k (256MB)
__device__ float g_phiq[(size_t)NG * CHQ * MF];          // 64MB
__device__ float g_stabk[NG];
__device__ float g_kv[NG * MF * ED];
__device__ float g_kvp[NG * KVSPLIT * MF * ED];
__device__ float g_ksum[NG * MF];
__device__ float g_pls[NG * CHQ];

__device__ __forceinline__ void atomicMaxF(float* addr, float val) {
    int* ai = (int*)addr;
    int old = *ai;
    while (__int_as_float(old) < val) {
        int assumed = old;
        old = atomicCAS(ai, assumed, __float_as_int(val));
        if (old == assumed) break;
    }
}

// ---------------- K0: init ----------------
__global__ void k_init() {
    int t = blockIdx.x * blockDim.x + threadIdx.x;
    if (t < NG) g_stabk[t] = -CUDART_INF_F;
}

// ---------------- K1: logk = k.projT - 0.5||k||^2 ; global max ----------------
struct S1 {
    float skT[ED][129];
    float spT[ED][129];
    float snorm[128];
    float wred[8];
};

__global__ void k_logk(const float* __restrict__ key, const float* __restrict__ proj) {
    extern __shared__ char smem_raw[];
    S1& sm = *reinterpret_cast<S1*>(smem_raw);
    int g = blockIdx.y;
    int c = g >> 5, b = (g >> 3) & 3, h = g & 7;
    int s0 = blockIdx.x * 128;
    int tid = threadIdx.x;

    for (int idx = tid; idx < 128 * ED; idx += 256) {
        int i = idx >> 6, e = idx & 63;
        sm.skT[e][i] = key[(((size_t)b * SEQ + (s0 + i)) * NHk + h) * ED + e];
    }
    for (int idx = tid; idx < MF * ED; idx += 256) {
        int m = idx >> 6, e = idx & 63;
        sm.spT[e][m] = proj[((size_t)c * MF + m) * ED + e];
    }
    __syncthreads();
    if (tid < 128) {
        float s = 0.f;
        #pragma unroll
        for (int e = 0; e < ED; e++) { float v = sm.skT[e][tid]; s += v * v; }
        sm.snorm[tid] = 0.5f * s;
    }
    __syncthreads();

    int tx = tid & 15, ty = tid >> 4;
    float acc[8][8];
    #pragma unroll
    for (int r = 0; r < 8; r++)
        #pragma unroll
        for (int c2 = 0; c2 < 8; c2++) acc[r][c2] = 0.f;

    for (int e = 0; e < ED; e++) {
        float a[8], bb[8];
        #pragma unroll
        for (int r = 0; r < 8; r++) a[r] = sm.skT[e][ty + 16 * r];
        #pragma unroll
        for (int c2 = 0; c2 < 8; c2++) bb[c2] = sm.spT[e][tx + 16 * c2];
        #pragma unroll
        for (int r = 0; r < 8; r++)
            #pragma unroll
            for (int c2 = 0; c2 < 8; c2++) acc[r][c2] = fmaf(a[r], bb[c2], acc[r][c2]);
    }

    float mx = -CUDART_INF_F;
    #pragma unroll
    for (int r = 0; r < 8; r++) {
        int i = ty + 16 * r;
        float nrm = sm.snorm[i];
        size_t rowoff = ((size_t)g * SEQ + (s0 + i)) * MF;
        #pragma unroll
        for (int c2 = 0; c2 < 8; c2++) {
            float v = acc[r][c2] - nrm;
            g_phik[rowoff + tx + 16 * c2] = v;
            mx = fmaxf(mx, v);
        }
    }
    #pragma unroll
    for (int o = 16; o > 0; o >>= 1) mx = fmaxf(mx, __shfl_xor_sync(0xffffffffu, mx, o));
    if ((tid & 31) == 0) sm.wred[tid >> 5] = mx;
    __syncthreads();
    if (tid == 0) {
        float m2 = sm.wred[0];
        #pragma unroll
        for (int w = 1; w < 8; w++) m2 = fmaxf(m2, sm.wred[w]);
        atomicMaxF(&g_stabk[g], m2);
    }
}

// ---------------- K2: phi_k = exp(logk - stab_k) in place ----------------
__global__ void k_expk() {
    size_t n = (size_t)NG * SEQ * MF;
    size_t stride = (size_t)gridDim.x * blockDim.x;
    for (size_t i = (size_t)blockIdx.x * blockDim.x + threadIdx.x; i < n; i += stride) {
        int g = (int)(i >> 19);   // SEQ*MF = 524288 = 2^19
        g_phik[i] = expf(g_phik[i] - g_stabk[g]);
    }
}

// ---------------- K3: kv partials (split over S) ----------------
__global__ void k_kv(const float* __restrict__ value) {
    __shared__ float ph[32][MF + 1];
    __shared__ float vv[32][ED + 1];
    int g = blockIdx.y;
    int b = (g >> 3) & 3, h = g & 7;
    int s0 = blockIdx.x * (SEQ / KVSPLIT);   // 512
    int tid = threadIdx.x;
    int tx = tid & 15, ty = tid >> 4;

    float acc[8][4];
    #pragma unroll
    for (int r = 0; r < 8; r++)
        #pragma unroll
        for (int c2 = 0; c2 < 4; c2++) acc[r][c2] = 0.f;

    for (int t = 0; t < (SEQ / KVSPLIT) / 32; t++) {
        int sb = s0 + t * 32;
        for (int idx = tid; idx < 32 * MF; idx += 256) {
            int s_ = idx >> 7, m = idx & 127;
            ph[s_][m] = g_phik[((size_t)g * SEQ + (sb + s_)) * MF + m];
        }
        for (int idx = tid; idx < 32 * ED; idx += 256) {
            int s_ = idx >> 6, e = idx & 63;
            vv[s_][e] = value[(((size_t)b * SEQ + (sb + s_)) * NHk + h) * ED + e];
        }
        __syncthreads();
        for (int s_ = 0; s_ < 32; s_++) {
            float a[8], bb[4];
            #pragma unroll
            for (int r = 0; r < 8; r++) a[r] = ph[s_][tx + 16 * r];
            #pragma unroll
            for (int c2 = 0; c2 < 4; c2++) bb[c2] = vv[s_][ty + 16 * c2];
            #pragma unroll
            for (int r = 0; r < 8; r++)
                #pragma unroll
                for (int c2 = 0; c2 < 4; c2++) acc[r][c2] = fmaf(a[r], bb[c2], acc[r][c2]);
        }
        __syncthreads();
    }
    #pragma unroll
    for (int r = 0; r < 8; r++)
        #pragma unroll
        for (int c2 = 0; c2 < 4; c2++) {
            int m = tx + 16 * r, e = ty + 16 * c2;
            g_kvp[(((size_t)g * KVSPLIT + blockIdx.x) * MF + m) * ED + e] = acc[r][c2];
        }
}

// ---------------- K4: reduce kv partials ----------------
__global__ void k_kvred() {
    int i = blockIdx.x * blockDim.x + threadIdx.x;
    if (i < NG * MF * ED) {
        int g = i / (MF * ED);
        int me = i % (MF * ED);
        float s = 0.f;
        #pragma unroll
        for (int p = 0; p < KVSPLIT; p++)
            s += g_kvp[((size_t)g * KVSPLIT + p) * MF * ED + me];
        g_kv[i] = s;
    }
}

// ---------------- K5: ksum ----------------
__global__ void k_ksum() {
    int g = blockIdx.x, m = threadIdx.x;
    const float* p = g_phik + (size_t)g * SEQ * MF + m;
    float s0 = 0.f, s1 = 0.f, s2 = 0.f, s3 = 0.f;
    for (int s_ = 0; s_ < SEQ; s_ += 4) {
        s0 += p[(size_t)s_ * MF];
        s1 += p[(size_t)(s_ + 1) * MF];
        s2 += p[(size_t)(s_ + 2) * MF];
        s3 += p[(size_t)(s_ + 3) * MF];
    }
    g_ksum[g * MF + m] = (s0 + s1) + (s2 + s3);
}

// ---------------- K6: phi_q, stab_q, pls ----------------
struct S3 {
    float sqT[ED][129];
    float spT[ED][129];
    float snorm[128];
    float rmax[128][17];
    float stabq[128];
};

__global__ void k_phiq(const float* __restrict__ query, const float* __restrict__ proj) {
    extern __shared__ char smem_raw[];
    S3& sm = *reinterpret_cast<S3*>(smem_raw);
    int g = blockIdx.y;
    int c = g >> 5, b = (g >> 3) & 3, h = g & 7;
    int q0 = blockIdx.x * 128;
    int tid = threadIdx.x;

    for (int idx = tid; idx < 128 * ED; idx += 256) {
        int i = idx >> 6, e = idx & 63;
        sm.sqT[e][i] = query[(((size_t)b * TT + (c * CHQ + q0 + i)) * NHk + h) * ED + e];
    }
    for (int idx = tid; idx < MF * ED; idx += 256) {
        int m = idx >> 6, e = idx & 63;
        sm.spT[e][m] = proj[((size_t)c * MF + m) * ED + e];
    }
    __syncthreads();
    if (tid < 128) {
        float s = 0.f;
        #pragma unroll
        for (int e = 0; e < ED; e++) { float v = sm.sqT[e][tid]; s += v * v; }
        sm.snorm[tid] = 0.5f * s;
    }
    __syncthreads();

    int tx = tid & 15, ty = tid >> 4;
    float acc[8][8];
    #pragma unroll
    for (int r = 0; r < 8; r++)
        #pragma unroll
        for (int c2 = 0; c2 < 8; c2++) acc[r][c2] = 0.f;

    for (int e = 0; e < ED; e++) {
        float a[8], bb[8];
        #pragma unroll
        for (int r = 0; r < 8; r++) a[r] = sm.sqT[e][ty + 16 * r];
        #pragma unroll
        for (int c2 = 0; c2 < 8; c2++) bb[c2] = sm.spT[e][tx + 16 * c2];
        #pragma unroll
        for (int r = 0; r < 8; r++)
            #pragma unroll
            for (int c2 = 0; c2 < 8; c2++) acc[r][c2] = fmaf(a[r], bb[c2], acc[r][c2]);
    }

    // logq = d - 0.5||q||^2 ; per-row (per-query) max over all MF features
    #pragma unroll
    for (int r = 0; r < 8; r++) {
        int i = ty + 16 * r;
        float nrm = sm.snorm[i];
        float pm = -CUDART_INF_F;
        #pragma unroll
        for (int c2 = 0; c2 < 8; c2++) {
            acc[r][c2] -= nrm;
            pm = fmaxf(pm, acc[r][c2]);
        }
        sm.rmax[i][tx] = pm;
    }
    __syncthreads();
    float skv = g_stabk[g];
    if (tid < 128) {
        float m2 = sm.rmax[tid][0];
        #pragma unroll
        for (int j = 1; j < 16; j++) m2 = fmaxf(m2, sm.rmax[tid][j]);
        sm.stabq[tid] = m2;
        g_pls[(size_t)g * CHQ + q0 + tid] = m2 + skv - LOGM;
    }
    __syncthreads();
    #pragma unroll
    for (int r = 0; r < 8; r++) {
        int i = ty + 16 * r;
        float st = sm.stabq[i];
        size_t rowoff = ((size_t)g * CHQ + q0 + i) * MF;
        #pragma unroll
        for (int c2 = 0; c2 < 8; c2++)
            g_phiq[rowoff + tx + 16 * c2] = expf(acc[r][c2] - st);
    }
}

// ---------------- K7: local windows + combination ----------------
struct S5 {
    float qT[ED][WW + 1];       // [64][33]
    float k3T[ED][97];
    float v3[96][ED + 1];       // [96][65]
    float pqT[MF][WW + 1];      // [128][33]
    float pk3T[MF][97];
    float kv[MF][ED];
    float sc[WW][100];
    float dp[WW][100];
    float ksum[MF];
    float lnorm[WW];
    float scl[WW];
    float plsr[WW];
};

__global__ void k_local(const float* __restrict__ query,
                        const float* __restrict__ key,
                        const float* __restrict__ value,
                        float* __restrict__ out) {
    extern __shared__ char smem_raw[];
    S5& sm = *reinterpret_cast<S5*>(smem_raw);
    int g = blockIdx.y;
    int n = blockIdx.x;
    int c = g >> 5, b = (g >> 3) & 3, h = g & 7;
    int tid = threadIdx.x;
    int t0 = n * WW;             // query offset within chunk
    int p0 = n * WW - WW;        // key position of j=0

    for (int idx = tid; idx < WW * ED; idx += 256) {
        int qi = idx >> 6, e = idx & 63;
        sm.qT[e][qi] = query[(((size_t)b * TT + (c * CHQ + t0 + qi)) * NHk + h) * ED + e];
    }
    for (int idx = tid; idx < 96 * ED; idx += 256) {
        int j = idx >> 6, e = idx & 63;
        int pos = p0 + j;
        float kvv = 0.f, vvv = 0.f;
        if (pos >= 0) {
            size_t base = (((size_t)b * SEQ + pos) * NHk + h) * ED + e;
            kvv = key[base];
            vvv = value[base];
        }
        sm.k3T[e][j] = kvv;
        sm.v3[j][e] = vvv;
    }
    for (int idx = tid; idx < WW * MF; idx += 256) {
        int qi = idx >> 7, m = idx & 127;
        sm.pqT[m][qi] = g_phiq[((size_t)g * CHQ + t0 + qi) * MF + m];
    }
    for (int idx = tid; idx < 96 * MF; idx += 256) {
        int j = idx >> 7, m = idx & 127;
        int pos = p0 + j;
        sm.pk3T[m][j] = (pos >= 0) ? g_phik[((size_t)g * SEQ + pos) * MF + m] : 0.f;
    }
    for (int idx = tid; idx < MF * ED; idx += 256)
        sm.kv[idx >> 6][idx & 63] = g_kv[(size_t)g * MF * ED + idx];
    if (tid < MF) sm.ksum[tid] = g_ksum[g * MF + tid];
    if (tid < WW) sm.plsr[tid] = g_pls[(size_t)g * CHQ + t0 + tid];
    __syncthreads();

    int lane = tid & 31, wrp = tid >> 5;

    // scores = q . k3  (masked -> -1e24)
    {
        float s[4][3];
        #pragma unroll
        for (int r = 0; r < 4; r++)
            #pragma unroll
            for (int jj = 0; jj < 3; jj++) s[r][jj] = 0.f;
        for (int e = 0; e < ED; e++) {
            float a[4], bb[3];
            #pragma unroll
            for (int r = 0; r < 4; r++) a[r] = sm.qT[e][wrp * 4 + r];
            #pragma unroll
            for (int jj = 0; jj < 3; jj++) bb[jj] = sm.k3T[e][lane + 32 * jj];
            #pragma unroll
            for (int r = 0; r < 4; r++)
                #pragma unroll
                for (int jj = 0; jj < 3; jj++) s[r][jj] = fmaf(a[r], bb[jj], s[r][jj]);
        }
        #pragma unroll
        for (int r = 0; r < 4; r++) {
            int qi = wrp * 4 + r;
            #pragma unroll
            for (int jj = 0; jj < 3; jj++) {
                int j = lane + 32 * jj;
                int rel = j - WW - qi;
                bool valid = (rel >= -16) && (rel < 16) && (p0 + j >= 0);
                sm.sc[qi][j] = valid ? s[r][jj] : -1e24f;
            }
        }
    }
    // dots_p = phi_q . phi_k3 (masked -> 0)
    {
        float d[4][3];
        #pragma unroll
        for (int r = 0; r < 4; r++)
            #pragma unroll
            for (int jj = 0; jj < 3; jj++) d[r][jj] = 0.f;
        for (int m = 0; m < MF; m++) {
            float a[4], bb[3];
            #pragma unroll
            for (int r = 0; r < 4; r++) a[r] = sm.pqT[m][wrp * 4 + r];
            #pragma unroll
            for (int jj = 0; jj < 3; jj++) bb[jj] = sm.pk3T[m][lane + 32 * jj];
            #pragma unroll
            for (int r = 0; r < 4; r++)
                #pragma unroll
                for (int jj = 0; jj < 3; jj++) d[r][jj] = fmaf(a[r], bb[jj], d[r][jj]);
        }
        #pragma unroll
        for (int r = 0; r < 4; r++) {
            int qi = wrp * 4 + r;
            #pragma unroll
            for (int jj = 0; jj < 3; jj++) {
                int j = lane + 32 * jj;
                int rel = j - WW - qi;
                bool valid = (rel >= -16) && (rel < 16) && (p0 + j >= 0);
                sm.dp[qi][j] = valid ? d[r][jj] : 0.f;
            }
        }
    }
    __syncthreads();

    // per-row: lse, dpsum, lr_1, log_norm, scale
    #pragma unroll
    for (int r = 0; r < 4; r++) {
        int row = wrp * 4 + r;
        float v0 = sm.sc[row][lane], v1 = sm.sc[row][lane + 32], v2 = sm.sc[row][lane + 64];
        float mx = fmaxf(fmaxf(v0, v1), v2);
        #pragma unroll
        for (int o = 16; o > 0; o >>= 1) mx = fmaxf(mx, __shfl_xor_sync(0xffffffffu, mx, o));
        float se = expf(v0 - mx) + expf(v1 - mx) + expf(v2 - mx);
        #pragma unroll
        for (int o = 16; o > 0; o >>= 1) se += __shfl_xor_sync(0xffffffffu, se, o);
        float lse = mx + logf(se);

        float ds = sm.dp[row][lane] + sm.dp[row][lane + 32] + sm.dp[row][lane + 64];
        #pragma unroll
        for (int o = 16; o > 0; o >>= 1) ds += __shfl_xor_sync(0xffffffffu, ds, o);

        float l1 = 0.f;
        #pragma unroll
        for (int mm = 0; mm < MF / 32; mm++)
            l1 += sm.pqT[lane + 32 * mm][row] * sm.ksum[lane + 32 * mm];
        #pragma unroll
        for (int o = 16; o > 0; o >>= 1) l1 += __shfl_xor_sync(0xffffffffu, l1, o);

        if (lane == 0) {
            float rem = fmaxf(l1 - ds, 1e-24f);
            float bq = logf(rem) + sm.plsr[row];
            float hi = fmaxf(lse, bq), lo = fminf(lse, bq);
            float ln = hi + log1pf(expf(lo - hi));
            sm.lnorm[row] = ln;
            sm.scl[row] = expf(sm.plsr[row] - ln);
        }
    }
    __syncthreads();

    // p_local in place
    for (int idx = tid; idx < WW * 96; idx += 256) {
        int qi = idx / 96, j = idx - qi * 96;
        sm.sc[qi][j] = expf(sm.sc[qi][j] - sm.lnorm[qi]);
    }
    __syncthreads();

    // out = p_local.v3 + (phi_q.kv - dots_p.v3) * scale
    float op[4][2], wn[4][2], lv[4][2];
    #pragma unroll
    for (int r = 0; r < 4; r++)
        #pragma unroll
        for (int ee = 0; ee < 2; ee++) { op[r][ee] = 0.f; wn[r][ee] = 0.f; lv[r][ee] = 0.f; }

    for (int j = 0; j < 96; j++) {
        float ap[4], ad[4], bv[2];
        #pragma unroll
        for (int r = 0; r < 4; r++) {
            ap[r] = sm.sc[wrp * 4 + r][j];
            ad[r] = sm.dp[wrp * 4 + r][j];
        }
        #pragma unroll
        for (int ee = 0; ee < 2; ee++) bv[ee] = sm.v3[j][lane + 32 * ee];
        #pragma unroll
        for (int r = 0; r < 4; r++)
            #pragma unroll
            for (int ee = 0; ee < 2; ee++) {
                op[r][ee] = fmaf(ap[r], bv[ee], op[r][ee]);
                wn[r][ee] = fmaf(ad[r], bv[ee], wn[r][ee]);
            }
    }
    for (int m = 0; m < MF; m++) {
        float aq[4], bk[2];
        #pragma unroll
        for (int r = 0; r < 4; r++) aq[r] = sm.pqT[m][wrp * 4 + r];
        #pragma unroll
        for (int ee = 0; ee < 2; ee++) bk[ee] = sm.kv[m][lane + 32 * ee];
        #pragma unroll
        for (int r = 0; r < 4; r++)
            #pragma unroll
            for (int ee = 0; ee < 2; ee++) lv[r][ee] = fmaf(aq[r], bk[ee], lv[r][ee]);
    }

    #pragma unroll
    for (int r = 0; r < 4; r++) {
        int qi = wrp * 4 + r;
        float scl = sm.scl[qi];
        size_t obase = (((size_t)b * NHk + h) * TT + (c * CHQ + t0 + qi)) * ED;
        #pragma unroll
        for (int ee = 0; ee < 2; ee++) {
            int e = lane + 32 * ee;
            out[obase + e] = op[r][ee] + (lv[r][ee] - wn[r][ee]) * scl;
        }
    }
}

// ---------------- launch ----------------
extern "C" void kernel_launch(void* const* d_in, const int* in_sizes, int n_in,
                              void* d_out, int out_size) {
    const float* query = (const float*)d_in[0];
    const float* key   = (const float*)d_in[1];
    const float* value = (const float*)d_in[2];
    const float* proj  = (const float*)d_in[3];
    float* out = (float*)d_out;

    cudaFuncSetAttribute(k_logk,  cudaFuncAttributeMaxDynamicSharedMemorySize, (int)sizeof(S1));
    cudaFuncSetAttribute(k_phiq,  cudaFuncAttributeMaxDynamicSharedMemorySize, (int)sizeof(S3));
    cudaFuncSetAttribute(k_local, cudaFuncAttributeMaxDynamicSharedMemorySize, (int)sizeof(S5));

    k_init<<<1, 256>>>();

    dim3 gl(SEQ / 128, NG);
    k_logk<<<gl, 256, sizeof(S1)>>>(key, proj);

    k_expk<<<8192, 256>>>();

    dim3 gk(KVSPLIT, NG);
    k_kv<<<gk, 256>>>(value);

    k_kvred<<<(NG * MF * ED + 255) / 256, 256>>>();

    k_ksum<<<NG, 128>>>();

    dim3 gq(CHQ / 128, NG);
    k_phiq<<<gq, 256, sizeof(S3)>>>(query, proj);

    dim3 g5(NBLOCK, NG);
    k_local<<<g5, 256, sizeof(S5)>>>(query, key, value, out);
}